// round 4
// baseline (speedup 1.0000x reference)
#include <cuda_runtime.h>

#define B_ 1024
#define T_ 512
#define C_ 48
#define HALF 24            // i-elements per thread (2-way split of i)
#define NTH 96             // 48 states x 2 halves, 3 full warps
#define ROW4 (C_ / 4)      // 12 float4 per output row

// 100 MB score-history scratch (allowed: __device__ global, no allocation)
__device__ float g_hist[(size_t)B_ * T_ * C_];

// monotonic float -> uint32 key (order-preserving)
__device__ __forceinline__ unsigned ordkey(float f) {
    unsigned u = __float_as_uint(f);
    return (u & 0x80000000u) ? ~u : (u | 0x80000000u);
}

// Viterbi decode, no stored backpointers.
// Forward: values-only max-plus recurrence; score rows streamed to g_hist.
// Backward: warp 0 recomputes the single needed argmax per step from the
// stored (bit-identical) score rows, with exact first-index tie-break via
// redux-max on ordered keys + two ballots. Warps 1-2 overlap the tail
// one-hot writes with the backtrack.
__global__ void __launch_bounds__(NTH, 8)
viterbi_kernel(const float* __restrict__ pot,
               const int* __restrict__ seqlen,
               const float* __restrict__ trans,
               float* __restrict__ out)
{
    __shared__ __align__(16) float trans_sm[C_ * C_];   // transposed [j][i], 9.2 KB
    __shared__ __align__(16) float sc[2][C_];           // double-buffered score
    __shared__ unsigned char tag_sh[T_];
    __shared__ int last_tag_sh;

    const int b   = blockIdx.x;
    const int tid = threadIdx.x;
    const int j   = tid >> 1;                  // state column 0..47
    const int h   = tid & 1;                   // half of i
    const int L   = seqlen[b];                 // 1 <= L < T_
    const float* potb  = pot + (size_t)b * T_ * C_;
    float*       histb = g_hist + (size_t)b * T_ * C_;

    // transposed transitions -> smem (backtrack reads trans_sm[tag*48 + i])
    for (int idx = tid; idx < C_ * C_; idx += NTH) {
        const int i  = idx % C_;
        const int jj = idx / C_;
        trans_sm[jj * C_ + i] = trans[i * C_ + jj];
    }

    // trans rows [h*24, h*24+24) of column j, in registers
    float tr[HALF];
#pragma unroll
    for (int k = 0; k < HALF; ++k) tr[k] = trans[(h * HALF + k) * C_ + j];

    const float sc0 = potb[j];
    if (h == 0) sc[0][j] = sc0;
    else        histb[j] = sc0;                // hist row 0
    __syncthreads();

    // ---------------- forward pass (values only) ----------------
    int cur = 0;
    float pn1 = (L > 1) ? potb[C_ + j] : 0.0f;
    float pn2 = (L > 2) ? potb[2 * C_ + j] : 0.0f;
    for (int t = 1; t < L; ++t) {
        const float potc = pn1;
        pn1 = pn2;
        if (t + 2 < L) pn2 = potb[(size_t)(t + 2) * C_ + j];

        const float4* sv = (const float4*)(sc[cur] + h * HALF);
        float v[HALF];
#pragma unroll
        for (int i4 = 0; i4 < HALF / 4; ++i4) {
            const float4 q = sv[i4];
            v[i4 * 4 + 0] = q.x + tr[i4 * 4 + 0];
            v[i4 * 4 + 1] = q.y + tr[i4 * 4 + 1];
            v[i4 * 4 + 2] = q.z + tr[i4 * 4 + 2];
            v[i4 * 4 + 3] = q.w + tr[i4 * 4 + 3];
        }
        // balanced max tree, FMNMX only (exact: fp max is order-independent)
#pragma unroll
        for (int s = 1; s < HALF; s *= 2)
#pragma unroll
            for (int k = 0; k + s < HALF; k += 2 * s)
                v[k] = fmaxf(v[k], v[k + s]);

        float best = fmaxf(v[0], __shfl_xor_sync(0xFFFFFFFFu, v[0], 1));
        const float ns = best + potc;
        if (h == 0) sc[cur ^ 1][j] = ns;       // next-step input
        else        histb[(size_t)t * C_ + j] = ns;  // history for backtrack
        __syncthreads();
        cur ^= 1;
    }

    // ---------------- final argmax (warp 0, first-index exact) ----------------
    if (tid < 32) {
        const int l = tid;
        const float sa = sc[cur][l];
        const float sb = (l < 16) ? sc[cur][32 + l] : -3.4e38f;
        const unsigned ka = ordkey(sa);
        const unsigned kb = ordkey(sb);
        const unsigned gm = __reduce_max_sync(0xFFFFFFFFu, ka > kb ? ka : kb);
        const unsigned ba = __ballot_sync(0xFFFFFFFFu, ka == gm);
        int tg;
        if (ba) tg = __ffs(ba) - 1;
        else {
            const unsigned bb = __ballot_sync(0xFFFFFFFFu, kb == gm);
            tg = __ffs(bb) - 1 + 32;
        }
        if (l == 0) last_tag_sh = tg;
    }
    __syncthreads();
    const int lt = last_tag_sh;

    const float4* ob4base = (const float4*)0;  // silence unused warnings pattern
    float4* ob4 = (float4*)(out + (size_t)b * T_ * C_);

    if (tid >= 32) {
        // ---- warps 1,2: tail one-hot rows t in [L-1, T) while warp 0 backtracks
        const int lane96 = tid - 32;           // 0..63
        const int start = (L - 1) * ROW4;
        const int total = T_ * ROW4;
        for (int idx = start + lane96; idx < total; idx += 64) {
            const int qq = idx % ROW4;
            const int base = qq * 4;
            float4 w;
            w.x = (lt == base + 0) ? 1.0f : 0.0f;
            w.y = (lt == base + 1) ? 1.0f : 0.0f;
            w.z = (lt == base + 2) ? 1.0f : 0.0f;
            w.w = (lt == base + 3) ? 1.0f : 0.0f;
            ob4[idx] = w;
        }
    } else {
        // ---- warp 0: backtrack, recomputing one argmax per step
        const int l = tid;
        // depth-3 prefetch pipeline of score rows (row r = hist[t-1] for t desc)
        float ra[3], rb[3];
#pragma unroll
        for (int k = 0; k < 3; ++k) {
            const int row = L - 2 - k;
            if (row >= 0) {
                ra[k] = histb[(size_t)row * C_ + l];
                rb[k] = (l < 16) ? histb[(size_t)row * C_ + 32 + l] : -3.4e38f;
            } else { ra[k] = 0.f; rb[k] = -3.4e38f; }
        }
        int tag = lt;
        int slot = 0;
        for (int t = L - 1; t >= 1; --t) {
            const float va = ra[slot];
            const float vb = rb[slot];
            const int nrow = t - 5;            // row (t-1) - 4? -> t-1-4+... 3 ahead: (t-3)-2
            // refill slot with row for iteration t-3 (its row index is t-4)
            if (t - 4 >= 0) {
                ra[slot] = histb[(size_t)(t - 4) * C_ + l];
                rb[slot] = (l < 16) ? histb[(size_t)(t - 4) * C_ + 32 + l] : -3.4e38f;
            }
            (void)nrow;
            slot = (slot == 2) ? 0 : slot + 1;

            const float ta = trans_sm[tag * C_ + l];
            const float sa = va + ta;
            float sb = -3.4e38f;
            if (l < 16) sb = vb + trans_sm[tag * C_ + 32 + l];

            const unsigned ka = ordkey(sa);
            const unsigned kb = ordkey(sb);
            const unsigned gm = __reduce_max_sync(0xFFFFFFFFu, ka > kb ? ka : kb);
            const unsigned ba = __ballot_sync(0xFFFFFFFFu, ka == gm);
            if (ba) tag = __ffs(ba) - 1;
            else {
                const unsigned bb = __ballot_sync(0xFFFFFFFFu, kb == gm);
                tag = __ffs(bb) - 1 + 32;
            }
            tag_sh[t - 1] = (unsigned char)tag;
        }
    }
    __syncthreads();

    // ---------------- head one-hot rows t in [0, L-1) ----------------
    const int headN = (L - 1) * ROW4;
    for (int idx = tid; idx < headN; idx += NTH) {
        const int t  = idx / ROW4;
        const int qq = idx - t * ROW4;
        const int tg = tag_sh[t];
        const int base = qq * 4;
        float4 w;
        w.x = (tg == base + 0) ? 1.0f : 0.0f;
        w.y = (tg == base + 1) ? 1.0f : 0.0f;
        w.z = (tg == base + 2) ? 1.0f : 0.0f;
        w.w = (tg == base + 3) ? 1.0f : 0.0f;
        ob4[idx] = w;
    }
    (void)ob4base;
}

extern "C" void kernel_launch(void* const* d_in, const int* in_sizes, int n_in,
                              void* d_out, int out_size)
{
    const float* pot    = (const float*)d_in[0];   // (B, T, C) float32
    const int*   slen   = (const int*)d_in[1];     // (B, 1)    int32
    const float* trans  = (const float*)d_in[2];   // (C, C)    float32
    float*       out    = (float*)d_out;           // (B, T, C) float32

    viterbi_kernel<<<B_, NTH>>>(pot, slen, trans, out);
}

// round 5
// speedup vs baseline: 1.9657x; 1.9657x over previous
#include <cuda_runtime.h>

#define B_ 1024
#define T_ 512
#define C_ 48
#define HALF 24            // i-elements per thread (2-way split of i)
#define NTH 96             // 48 states x 2 halves, 3 full warps
#define ROW4 (C_ / 4)      // 12 float4 per output row

// monotonic float -> uint32 key (order-preserving)
__device__ __forceinline__ unsigned ordkey(float f) {
    unsigned u = __float_as_uint(f);
    return (u & 0x80000000u) ? ~u : (u | 0x80000000u);
}

// Viterbi decode: one block per batch element.
// Thread (j,h): j = tid>>1 (state column), h = tid&1 (half of i).
// Streaming tournament argmax (6 group winners live -> no spills), strict-'>'
// merges preserve first-index tie-break exactly. Backpointers in shared;
// warp 0 chases them while warps 1-2 write the one-hot tail.
__global__ void __launch_bounds__(NTH, 7)
viterbi_kernel(const float* __restrict__ pot,
               const int* __restrict__ seqlen,
               const float* __restrict__ trans,
               float* __restrict__ out)
{
    __shared__ unsigned char bp_sh[T_ * C_];          // 24576 B backpointers
    __shared__ unsigned char tag_sh[T_];              // decoded tags
    __shared__ __align__(16) float sc[2][C_];         // double-buffered score
    __shared__ int last_tag_sh;

    const int b   = blockIdx.x;
    const int tid = threadIdx.x;
    const int j   = tid >> 1;                         // state column 0..47
    const int h   = tid & 1;                          // half 0..1
    const int L   = seqlen[b];                        // 1 <= L < T_
    const float* potb = pot + (size_t)b * T_ * C_;

    // trans rows [h*24, h*24+24) of column j, in registers
    float tr[HALF];
#pragma unroll
    for (int k = 0; k < HALF; ++k) tr[k] = trans[(h * HALF + k) * C_ + j];

    if (h == 0) sc[0][j] = potb[j];                   // init score = potentials[:,0]
    __syncthreads();

    // ---------------- forward pass ----------------
    int cur = 0;
    float pn1 = (L > 1) ? potb[C_ + j] : 0.0f;        // prefetch t=1
    float pn2 = (L > 2) ? potb[2 * C_ + j] : 0.0f;    // prefetch t=2
    for (int t = 1; t < L; ++t) {
        const float potc = pn1;
        pn1 = pn2;
        if (t + 2 < L) pn2 = potb[(size_t)(t + 2) * C_ + j];

        const float4* sv = (const float4*)(sc[cur] + h * HALF);

        // streaming tournament: fold each float4 group to one winner
        float gv[6]; int gi[6];
#pragma unroll
        for (int g = 0; g < 6; ++g) {
            const float4 q = sv[g];
            const int ib = g * 4;
            const float a = q.x + tr[ib + 0];
            const float b2 = q.y + tr[ib + 1];
            const float c = q.z + tr[ib + 2];
            const float d = q.w + tr[ib + 3];
            const float v1 = fmaxf(a, b2);
            const int   i1 = (b2 > a) ? ib + 1 : ib;
            const float v2 = fmaxf(c, d);
            const int   i2 = (d > c) ? ib + 3 : ib + 2;
            gv[g] = fmaxf(v1, v2);
            gi[g] = (v2 > v1) ? i2 : i1;
        }
        // 6 -> 3 -> 1 (index order preserved: strict '>' keeps first index)
        const float u0 = fmaxf(gv[0], gv[1]); const int q0 = (gv[1] > gv[0]) ? gi[1] : gi[0];
        const float u1 = fmaxf(gv[2], gv[3]); const int q1 = (gv[3] > gv[2]) ? gi[3] : gi[2];
        const float u2 = fmaxf(gv[4], gv[5]); const int q2 = (gv[5] > gv[4]) ? gi[5] : gi[4];
        const float w0 = fmaxf(u0, u1);       const int k0 = (u1 > u0) ? q1 : q0;
        const float best = fmaxf(w0, u2);
        const int   lbi  = ((u2 > w0) ? q2 : k0) + h * HALF;

        // combine halves within the lane pair (value desc, then index asc)
        const float ob = __shfl_xor_sync(0xFFFFFFFFu, best, 1);
        const int   oi = __shfl_xor_sync(0xFFFFFFFFu, lbi,  1);
        const bool take_other = (ob > best) || (ob == best && oi < lbi);
        const float wbest = take_other ? ob : best;
        const int   wbi   = take_other ? oi : lbi;

        if (h == 0) {
            bp_sh[t * C_ + j] = (unsigned char)wbi;
            sc[cur ^ 1][j] = wbest + potc;
        }
        __syncthreads();
        cur ^= 1;
    }

    // ---------------- final argmax (warp 0, first-index exact) ----------------
    if (tid < 32) {
        const float sa = sc[cur][tid];
        const float sb = (tid < 16) ? sc[cur][32 + tid] : -3.4e38f;
        const unsigned ka = ordkey(sa);
        const unsigned kb = ordkey(sb);
        const unsigned gm = __reduce_max_sync(0xFFFFFFFFu, ka > kb ? ka : kb);
        const unsigned ba = __ballot_sync(0xFFFFFFFFu, ka == gm);
        int tg;
        if (ba) tg = __ffs(ba) - 1;
        else {
            const unsigned bb = __ballot_sync(0xFFFFFFFFu, kb == gm);
            tg = __ffs(bb) - 1 + 32;
        }
        if (tid == 0) last_tag_sh = tg;
    }
    __syncthreads();
    const int lt = last_tag_sh;

    float4* ob4 = (float4*)(out + (size_t)b * T_ * C_);

    if (tid >= 32) {
        // ---- warps 1,2: one-hot tail rows t in [L-1, T) while warp 0 backtracks
        const int lane64 = tid - 32;               // 0..63
        const int start = (L - 1) * ROW4;
        for (int idx = start + lane64; idx < T_ * ROW4; idx += 64) {
            const int qq = idx % ROW4;
            const int base = qq * 4;
            float4 w;
            w.x = (lt == base + 0) ? 1.0f : 0.0f;
            w.y = (lt == base + 1) ? 1.0f : 0.0f;
            w.z = (lt == base + 2) ? 1.0f : 0.0f;
            w.w = (lt == base + 3) ? 1.0f : 0.0f;
            ob4[idx] = w;
        }
    } else if (tid == 0) {
        // ---- warp 0 lane 0: bp chase (LDS-latency chain, ~30 cyc/step)
        int tag = lt;
        for (int t = L - 1; t >= 1; --t) {
            tag = bp_sh[t * C_ + tag];
            tag_sh[t - 1] = (unsigned char)tag;
        }
    }
    __syncthreads();

    // ---------------- one-hot head rows t in [0, L-1) ----------------
    const int headN = (L - 1) * ROW4;
    for (int idx = tid; idx < headN; idx += NTH) {
        const int t  = idx / ROW4;
        const int qq = idx - t * ROW4;
        const int tg = tag_sh[t];
        const int base = qq * 4;
        float4 w;
        w.x = (tg == base + 0) ? 1.0f : 0.0f;
        w.y = (tg == base + 1) ? 1.0f : 0.0f;
        w.z = (tg == base + 2) ? 1.0f : 0.0f;
        w.w = (tg == base + 3) ? 1.0f : 0.0f;
        ob4[idx] = w;
    }
}

extern "C" void kernel_launch(void* const* d_in, const int* in_sizes, int n_in,
                              void* d_out, int out_size)
{
    const float* pot    = (const float*)d_in[0];   // (B, T, C) float32
    const int*   slen   = (const int*)d_in[1];     // (B, 1)    int32
    const float* trans  = (const float*)d_in[2];   // (C, C)    float32
    float*       out    = (float*)d_out;           // (B, T, C) float32

    viterbi_kernel<<<B_, NTH>>>(pot, slen, trans, out);
}